// round 1
// baseline (speedup 1.0000x reference)
#include <cuda_runtime.h>
#include <cstdint>

// Problem constants
#define BB    4
#define TT    4096
#define CC    1024
#define MTOT  (BB*TT)          // 16384 rows
#define NCHUNK 64
#define LCH   (TT/NCHUNK)      // 64 steps per chunk
#define NEG_INF_F (-1e38f)

// ---------------------------------------------------------------------------
// Scratch (static __device__ arrays; no allocation in kernel_launch)
// ---------------------------------------------------------------------------
__device__ float g_k   [(size_t)MTOT*CC];
__device__ float g_v   [(size_t)MTOT*CC];
__device__ float g_r   [(size_t)MTOT*CC];   // sigmoid already applied
__device__ float g_rwkv[(size_t)MTOT*CC];

__device__ float g_csa[BB*NCHUNK*CC];   // chunk-local states (from zero state)
__device__ float g_csb[BB*NCHUNK*CC];
__device__ float g_csp[BB*NCHUNK*CC];
__device__ float g_ia [BB*NCHUNK*CC];   // true initial state of each chunk
__device__ float g_ib [BB*NCHUNK*CC];
__device__ float g_ip [BB*NCHUNK*CC];

// ---------------------------------------------------------------------------
// tf32 helpers
// ---------------------------------------------------------------------------
__device__ __forceinline__ uint32_t f2tf32(float x) {
    uint32_t y;
    asm("cvt.rna.tf32.f32 %0, %1;" : "=r"(y) : "f"(x));
    return y;
}

__device__ __forceinline__ void mma_tf32(float* d, const uint32_t* a, const uint32_t* b) {
    asm volatile(
        "mma.sync.aligned.m16n8k8.row.col.f32.tf32.tf32.f32 "
        "{%0,%1,%2,%3}, {%4,%5,%6,%7}, {%8,%9}, {%0,%1,%2,%3};"
        : "+f"(d[0]), "+f"(d[1]), "+f"(d[2]), "+f"(d[3])
        : "r"(a[0]), "r"(a[1]), "r"(a[2]), "r"(a[3]),
          "r"(b[0]), "r"(b[1]));
}

// ---------------------------------------------------------------------------
// tf32 GEMM:  C[m,n] = sum_k A[m,k] * W[n,k]   (torch Linear convention)
// M=16384, N=1024, K=1024 per launch.  Tile 128x128x16, 256 threads,
// warp grid 2x4 (warp tile 64x32), mma.sync m16n8k8.
// srcSel: 0 -> A = Aext (x), 1 -> A = g_rwkv
// dstSel: 0/1/2 -> g_k/g_v/g_r, 3 -> Cext (d_out)
// applySig: sigmoid epilogue (receptance)
// ---------------------------------------------------------------------------
__global__ void __launch_bounds__(256) gemm_tf32(
    const float* __restrict__ Aext, const float* __restrict__ W,
    float* __restrict__ Cext, int srcSel, int dstSel, int applySig)
{
    const float* A = srcSel ? g_rwkv : Aext;
    float* Cp = (dstSel == 0) ? g_k : (dstSel == 1) ? g_v : (dstSel == 2) ? g_r : Cext;

    __shared__ float As[128][20];   // [m][k], pad 20 -> conflict-free frag loads
    __shared__ float Bs[128][20];   // [n][k]

    const int tid  = threadIdx.x;
    const int warp = tid >> 5, lane = tid & 31;
    const int wRow = (warp >> 2) * 64;   // 2 warp-rows
    const int wCol = (warp & 3)  * 32;   // 4 warp-cols
    const int grp  = lane >> 2, th4 = lane & 3;
    const int bm = blockIdx.x * 128;
    const int bn = blockIdx.y * 128;

    float acc[4][4][4];
    #pragma unroll
    for (int mt = 0; mt < 4; mt++)
        #pragma unroll
        for (int nt = 0; nt < 4; nt++)
            #pragma unroll
            for (int i = 0; i < 4; i++) acc[mt][nt][i] = 0.f;

    const int lrow = tid >> 2;        // 0..63
    const int lcf  = (tid & 3) * 4;   // 0,4,8,12

    for (int k0 = 0; k0 < CC; k0 += 16) {
        // cooperative load + tf32 round-to-nearest
        #pragma unroll
        for (int j = 0; j < 2; j++) {
            int row = lrow + 64 * j;
            float4 va = *(const float4*)&A[(bm + row) * CC + k0 + lcf];
            float4 vb = *(const float4*)&W[(bn + row) * CC + k0 + lcf];
            float4 ta = make_float4(__uint_as_float(f2tf32(va.x)),
                                    __uint_as_float(f2tf32(va.y)),
                                    __uint_as_float(f2tf32(va.z)),
                                    __uint_as_float(f2tf32(va.w)));
            float4 tb = make_float4(__uint_as_float(f2tf32(vb.x)),
                                    __uint_as_float(f2tf32(vb.y)),
                                    __uint_as_float(f2tf32(vb.z)),
                                    __uint_as_float(f2tf32(vb.w)));
            *(float4*)&As[row][lcf] = ta;
            *(float4*)&Bs[row][lcf] = tb;
        }
        __syncthreads();

        #pragma unroll
        for (int ks = 0; ks < 2; ks++) {
            const int kk = ks * 8;
            uint32_t af[4][4], bf[4][2];
            #pragma unroll
            for (int mt = 0; mt < 4; mt++) {
                const int r = wRow + mt * 16;
                af[mt][0] = __float_as_uint(As[r + grp    ][kk + th4    ]);
                af[mt][1] = __float_as_uint(As[r + grp + 8][kk + th4    ]);
                af[mt][2] = __float_as_uint(As[r + grp    ][kk + th4 + 4]);
                af[mt][3] = __float_as_uint(As[r + grp + 8][kk + th4 + 4]);
            }
            #pragma unroll
            for (int nt = 0; nt < 4; nt++) {
                const int cn = wCol + nt * 8;
                bf[nt][0] = __float_as_uint(Bs[cn + grp][kk + th4    ]);
                bf[nt][1] = __float_as_uint(Bs[cn + grp][kk + th4 + 4]);
            }
            #pragma unroll
            for (int mt = 0; mt < 4; mt++)
                #pragma unroll
                for (int nt = 0; nt < 4; nt++)
                    mma_tf32(acc[mt][nt], af[mt], bf[nt]);
        }
        __syncthreads();
    }

    // epilogue
    #pragma unroll
    for (int mt = 0; mt < 4; mt++) {
        #pragma unroll
        for (int nt = 0; nt < 4; nt++) {
            int r0 = bm + wRow + mt * 16 + grp;
            int c0 = bn + wCol + nt * 8 + th4 * 2;
            float v0 = acc[mt][nt][0], v1 = acc[mt][nt][1];
            float v2 = acc[mt][nt][2], v3 = acc[mt][nt][3];
            if (applySig) {
                v0 = 1.f / (1.f + __expf(-v0));
                v1 = 1.f / (1.f + __expf(-v1));
                v2 = 1.f / (1.f + __expf(-v2));
                v3 = 1.f / (1.f + __expf(-v3));
            }
            *(float2*)&Cp[r0 * CC + c0]       = make_float2(v0, v1);
            *(float2*)&Cp[(r0 + 8) * CC + c0] = make_float2(v2, v3);
        }
    }
}

// ---------------------------------------------------------------------------
// S1: per-(b,chunk,c) chunk-local state from zero state
// ---------------------------------------------------------------------------
__global__ void __launch_bounds__(256) scan_chunk_state(const float* __restrict__ td)
{
    const int g = blockIdx.x * 256 + threadIdx.x;       // 262144 threads
    const int c = g & (CC - 1);
    const int chunk = (g >> 10) & (NCHUNK - 1);
    const int b = g >> 16;

    const float w = __expf(td[c]);
    const int base = (b * TT + chunk * LCH) * CC + c;

    float aa = 0.f, bb = 0.f, pp = NEG_INF_F;
    #pragma unroll 4
    for (int l = 0; l < LCH; l++) {
        float kt = g_k[base + l * CC];
        float vt = g_v[base + l * CC];
        float ww2 = pp - w;
        float p2  = fmaxf(ww2, kt);
        float e1  = __expf(ww2 - p2);
        float e2  = __expf(kt - p2);
        aa = e1 * aa + e2 * vt;
        bb = e1 * bb + e2;
        pp = p2;
    }
    const int idx = (b * NCHUNK + chunk) * CC + c;
    g_csa[idx] = aa; g_csb[idx] = bb; g_csp[idx] = pp;
}

// ---------------------------------------------------------------------------
// S2: sequentially compose chunk transforms per (b,c); record chunk-initial
// states; write final (aa,bb,pp) to d_out tail.
// ---------------------------------------------------------------------------
__global__ void __launch_bounds__(256) scan_combine(
    const float* __restrict__ td,
    const float* __restrict__ aa0, const float* __restrict__ bb0,
    const float* __restrict__ pp0, float* __restrict__ out_states)
{
    const int g = blockIdx.x * 256 + threadIdx.x;   // 4096 threads
    const int c = g & (CC - 1);
    const int b = g >> 10;

    const float w  = __expf(td[c]);
    const float wL = w * (float)LCH;

    float aa = aa0[g], bb = bb0[g], pp = pp0[g];
    for (int ch = 0; ch < NCHUNK; ch++) {
        const int idx = (b * NCHUNK + ch) * CC + c;
        g_ia[idx] = aa; g_ib[idx] = bb; g_ip[idx] = pp;
        // compose: A_out = e^{-wL} * A_in + S   (log-sum-exp stabilized)
        float ppd = pp - wL;
        float sp  = g_csp[idx];
        float q   = fmaxf(ppd, sp);
        float e1  = __expf(ppd - q);
        float e2  = __expf(sp - q);
        aa = e1 * aa + e2 * g_csa[idx];
        bb = e1 * bb + e2 * g_csb[idx];
        pp = q;
    }
    out_states[g]               = aa;   // aa  [B,C]
    out_states[BB * CC + g]     = bb;   // bb
    out_states[2 * BB * CC + g] = pp;   // pp
}

// ---------------------------------------------------------------------------
// S3: replay each chunk from its true initial state, emit sigmoid(r)*wkv
// ---------------------------------------------------------------------------
__global__ void __launch_bounds__(256) scan_output(
    const float* __restrict__ td, const float* __restrict__ tf)
{
    const int g = blockIdx.x * 256 + threadIdx.x;
    const int c = g & (CC - 1);
    const int chunk = (g >> 10) & (NCHUNK - 1);
    const int b = g >> 16;

    const float w = __expf(td[c]);
    const float u = tf[c];
    const int idx = (b * NCHUNK + chunk) * CC + c;
    const int base = (b * TT + chunk * LCH) * CC + c;

    float aa = g_ia[idx], bb = g_ib[idx], pp = g_ip[idx];
    #pragma unroll 4
    for (int l = 0; l < LCH; l++) {
        float kt = g_k[base + l * CC];
        float vt = g_v[base + l * CC];
        float rt = g_r[base + l * CC];
        // output
        float ww = u + kt;
        float p  = fmaxf(pp, ww);
        float e1 = __expf(pp - p);
        float e2 = __expf(ww - p);
        float wkv = (e1 * aa + e2 * vt) / (e1 * bb + e2);
        g_rwkv[base + l * CC] = rt * wkv;
        // state update
        float ww2 = pp - w;
        float p2  = fmaxf(ww2, kt);
        float e1b = __expf(ww2 - p2);
        float e2b = __expf(kt - p2);
        aa = e1b * aa + e2b * vt;
        bb = e1b * bb + e2b;
        pp = p2;
    }
}

// ---------------------------------------------------------------------------
// Launcher
// ---------------------------------------------------------------------------
extern "C" void kernel_launch(void* const* d_in, const int* in_sizes, int n_in,
                              void* d_out, int out_size)
{
    const float* x        = (const float*)d_in[0];
    const float* key_w    = (const float*)d_in[1];
    const float* value_w  = (const float*)d_in[2];
    const float* recept_w = (const float*)d_in[3];
    const float* output_w = (const float*)d_in[4];
    const float* td       = (const float*)d_in[5];  // time_decay
    const float* tf       = (const float*)d_in[6];  // time_first
    const float* aa0      = (const float*)d_in[7];
    const float* bb0      = (const float*)d_in[8];
    const float* pp0      = (const float*)d_in[9];
    float* out = (float*)d_out;

    dim3 gg(MTOT / 128, CC / 128);   // 128 x 8

    // projections
    gemm_tf32<<<gg, 256>>>(x, key_w,    nullptr, 0, 0, 0);
    gemm_tf32<<<gg, 256>>>(x, value_w,  nullptr, 0, 1, 0);
    gemm_tf32<<<gg, 256>>>(x, recept_w, nullptr, 0, 2, 1);

    // chunked WKV scan
    scan_chunk_state<<<(BB * NCHUNK * CC) / 256, 256>>>(td);
    scan_combine<<<(BB * CC) / 256, 256>>>(td, aa0, bb0, pp0,
                                           out + (size_t)MTOT * CC);
    scan_output<<<(BB * NCHUNK * CC) / 256, 256>>>(td, tf);

    // output projection
    gemm_tf32<<<gg, 256>>>(nullptr, output_w, out, 1, 3, 0);
}

// round 14
// speedup vs baseline: 1.4515x; 1.4515x over previous
#include <cuda_runtime.h>
#include <cstdint>

// Round-12 experiment, resubmitted (broker infra failed before compile/run in
// rounds 12 and 13; no kernel-side signal yet). Round-1 structure with a
// single perf delta: K-stage 32, batch-8 loads, all load registers dead
// before each barrier (empirical no-extra-liveness spill rule).

// ---------------------------------------------------------------------------
// Problem constants
// ---------------------------------------------------------------------------
#define BB    4
#define TT    4096
#define CC    1024
#define MTOT  (BB*TT)          // 16384 rows
#define NCHUNK 64
#define LCH   (TT/NCHUNK)      // 64
#define NEG_INF_F (-1e38f)

// ---------------------------------------------------------------------------
// Scratch (identical set to the round-1 passing kernel)
// ---------------------------------------------------------------------------
__device__ float g_k   [(size_t)MTOT*CC];
__device__ float g_v   [(size_t)MTOT*CC];
__device__ float g_r   [(size_t)MTOT*CC];   // sigmoid already applied
__device__ float g_rwkv[(size_t)MTOT*CC];

__device__ float g_csa[BB*NCHUNK*CC];
__device__ float g_csb[BB*NCHUNK*CC];
__device__ float g_csp[BB*NCHUNK*CC];
__device__ float g_ia [BB*NCHUNK*CC];
__device__ float g_ib [BB*NCHUNK*CC];
__device__ float g_ip [BB*NCHUNK*CC];

// ---------------------------------------------------------------------------
// tf32 helpers (round-1 verbatim)
// ---------------------------------------------------------------------------
__device__ __forceinline__ uint32_t f2tf32(float x) {
    uint32_t y;
    asm("cvt.rna.tf32.f32 %0, %1;" : "=r"(y) : "f"(x));
    return y;
}
__device__ __forceinline__ float4 cvt4(float4 v) {
    return make_float4(__uint_as_float(f2tf32(v.x)), __uint_as_float(f2tf32(v.y)),
                       __uint_as_float(f2tf32(v.z)), __uint_as_float(f2tf32(v.w)));
}
__device__ __forceinline__ void mma_tf32(float* d, const uint32_t* a, const uint32_t* b) {
    asm volatile(
        "mma.sync.aligned.m16n8k8.row.col.f32.tf32.tf32.f32 "
        "{%0,%1,%2,%3}, {%4,%5,%6,%7}, {%8,%9}, {%0,%1,%2,%3};"
        : "+f"(d[0]), "+f"(d[1]), "+f"(d[2]), "+f"(d[3])
        : "r"(a[0]), "r"(a[1]), "r"(a[2]), "r"(a[3]),
          "r"(b[0]), "r"(b[1]));
}

// ---------------------------------------------------------------------------
// tf32 GEMM:  C[m,n] = sum_k A[m,k] * W[n,k]   (torch Linear convention)
// Tile 128x128, 256 threads, warp grid 2x4 (warp tile 64x32), m16n8k8.
// K-stage 32 with batch-8 loads; load regs dead before each __syncthreads().
// srcSel: 0 -> A = Aext (x), 1 -> A = g_rwkv
// dstSel: 0/1/2 -> g_k/g_v/g_r, 3 -> Cext (d_out)
// applySig: sigmoid epilogue (receptance)
// ---------------------------------------------------------------------------
__global__ void __launch_bounds__(256) gemm_tf32(
    const float* __restrict__ Aext, const float* __restrict__ W,
    float* __restrict__ Cext, int srcSel, int dstSel, int applySig)
{
    const float* A = srcSel ? g_rwkv : Aext;
    float* Cp = (dstSel == 0) ? g_k : (dstSel == 1) ? g_v : (dstSel == 2) ? g_r : Cext;

    __shared__ float As[128][36];   // [m][k], stride 36 -> conflict-free frags
    __shared__ float Bs[128][36];   // [n][k]

    const int tid  = threadIdx.x;
    const int warp = tid >> 5, lane = tid & 31;
    const int wRow = (warp >> 2) * 64;   // 2 warp-rows
    const int wCol = (warp & 3)  * 32;   // 4 warp-cols
    const int grp  = lane >> 2, th4 = lane & 3;
    const int bm = blockIdx.x * 128;
    const int bn = blockIdx.y * 128;

    float acc[4][4][4];
    #pragma unroll
    for (int mt = 0; mt < 4; mt++)
        #pragma unroll
        for (int nt = 0; nt < 4; nt++)
            #pragma unroll
            for (int i = 0; i < 4; i++) acc[mt][nt][i] = 0.f;

    // loader: 128 rows x 8 chunks (16B) per matrix per K32 stage;
    // 256 threads -> 4 row-slots each (rows row, row+32, row+64, row+96)
    const int row = tid >> 3;         // 0..31
    const int ch  = tid & 7;          // 0..7 (16B chunk)
    const float* apA = A + (size_t)(bm + row) * CC + ch * 4;
    const float* apB = W + (size_t)(bn + row) * CC + ch * 4;
    const size_t rs32 = (size_t)32 * CC;

    #pragma unroll 1
    for (int kt = 0; kt < 32; kt++) {
        const int ko = kt * 32;
        // batch-8 global loads (MLP=8), then cvt+store; regs dead before sync
        {
            float4 a0 = *(const float4*)(apA + ko);
            float4 a1 = *(const float4*)(apA + rs32 + ko);
            float4 a2 = *(const float4*)(apA + 2 * rs32 + ko);
            float4 a3 = *(const float4*)(apA + 3 * rs32 + ko);
            float4 b0 = *(const float4*)(apB + ko);
            float4 b1 = *(const float4*)(apB + rs32 + ko);
            float4 b2 = *(const float4*)(apB + 2 * rs32 + ko);
            float4 b3 = *(const float4*)(apB + 3 * rs32 + ko);
            *(float4*)&As[row     ][ch * 4] = cvt4(a0);
            *(float4*)&As[row + 32][ch * 4] = cvt4(a1);
            *(float4*)&As[row + 64][ch * 4] = cvt4(a2);
            *(float4*)&As[row + 96][ch * 4] = cvt4(a3);
            *(float4*)&Bs[row     ][ch * 4] = cvt4(b0);
            *(float4*)&Bs[row + 32][ch * 4] = cvt4(b1);
            *(float4*)&Bs[row + 64][ch * 4] = cvt4(b2);
            *(float4*)&Bs[row + 96][ch * 4] = cvt4(b3);
        }
        __syncthreads();

        // compute K=32 as 4 x K8  (round-1 fragment layout)
        #pragma unroll
        for (int ks = 0; ks < 4; ks++) {
            const int kk = ks * 8;
            uint32_t af[4][4], bf[4][2];
            #pragma unroll
            for (int mt = 0; mt < 4; mt++) {
                const int r = wRow + mt * 16;
                af[mt][0] = __float_as_uint(As[r + grp    ][kk + th4    ]);
                af[mt][1] = __float_as_uint(As[r + grp + 8][kk + th4    ]);
                af[mt][2] = __float_as_uint(As[r + grp    ][kk + th4 + 4]);
                af[mt][3] = __float_as_uint(As[r + grp + 8][kk + th4 + 4]);
            }
            #pragma unroll
            for (int nt = 0; nt < 4; nt++) {
                const int cn = wCol + nt * 8;
                bf[nt][0] = __float_as_uint(Bs[cn + grp][kk + th4    ]);
                bf[nt][1] = __float_as_uint(Bs[cn + grp][kk + th4 + 4]);
            }
            #pragma unroll
            for (int mt = 0; mt < 4; mt++)
                #pragma unroll
                for (int nt = 0; nt < 4; nt++)
                    mma_tf32(acc[mt][nt], af[mt], bf[nt]);
        }
        __syncthreads();
    }

    // epilogue (round-1 verbatim)
    #pragma unroll
    for (int mt = 0; mt < 4; mt++) {
        #pragma unroll
        for (int nt = 0; nt < 4; nt++) {
            int r0 = bm + wRow + mt * 16 + grp;
            int c0 = bn + wCol + nt * 8 + th4 * 2;
            float v0 = acc[mt][nt][0], v1 = acc[mt][nt][1];
            float v2 = acc[mt][nt][2], v3 = acc[mt][nt][3];
            if (applySig) {
                v0 = 1.f / (1.f + __expf(-v0));
                v1 = 1.f / (1.f + __expf(-v1));
                v2 = 1.f / (1.f + __expf(-v2));
                v3 = 1.f / (1.f + __expf(-v3));
            }
            *(float2*)&Cp[(size_t)r0 * CC + c0]       = make_float2(v0, v1);
            *(float2*)&Cp[(size_t)(r0 + 8) * CC + c0] = make_float2(v2, v3);
        }
    }
}

// ---------------------------------------------------------------------------
// S1: per-(b,chunk,c) chunk-local state from zero state  (round-1 verbatim)
// ---------------------------------------------------------------------------
__global__ void __launch_bounds__(256) scan_chunk_state(const float* __restrict__ td)
{
    const int g = blockIdx.x * 256 + threadIdx.x;       // 262144 threads
    const int c = g & (CC - 1);
    const int chunk = (g >> 10) & (NCHUNK - 1);
    const int b = g >> 16;

    const float w = __expf(td[c]);
    const int base = (b * TT + chunk * LCH) * CC + c;

    float aa = 0.f, bb = 0.f, pp = NEG_INF_F;
    #pragma unroll 4
    for (int l = 0; l < LCH; l++) {
        float kt = g_k[base + l * CC];
        float vt = g_v[base + l * CC];
        float ww2 = pp - w;
        float p2  = fmaxf(ww2, kt);
        float e1  = __expf(ww2 - p2);
        float e2  = __expf(kt - p2);
        aa = e1 * aa + e2 * vt;
        bb = e1 * bb + e2;
        pp = p2;
    }
    const int idx = (b * NCHUNK + chunk) * CC + c;
    g_csa[idx] = aa; g_csb[idx] = bb; g_csp[idx] = pp;
}

// ---------------------------------------------------------------------------
// S2: compose chunk transforms; record chunk-initial states  (round-1 verbatim)
// ---------------------------------------------------------------------------
__global__ void __launch_bounds__(256) scan_combine(
    const float* __restrict__ td,
    const float* __restrict__ aa0, const float* __restrict__ bb0,
    const float* __restrict__ pp0, float* __restrict__ out_states)
{
    const int g = blockIdx.x * 256 + threadIdx.x;   // 4096 threads
    const int c = g & (CC - 1);
    const int b = g >> 10;

    const float w  = __expf(td[c]);
    const float wL = w * (float)LCH;

    float aa = aa0[g], bb = bb0[g], pp = pp0[g];
    for (int ch = 0; ch < NCHUNK; ch++) {
        const int idx = (b * NCHUNK + ch) * CC + c;
        g_ia[idx] = aa; g_ib[idx] = bb; g_ip[idx] = pp;
        float ppd = pp - wL;
        float sp  = g_csp[idx];
        float q   = fmaxf(ppd, sp);
        float e1  = __expf(ppd - q);
        float e2  = __expf(sp - q);
        aa = e1 * aa + e2 * g_csa[idx];
        bb = e1 * bb + e2 * g_csb[idx];
        pp = q;
    }
    out_states[g]               = aa;
    out_states[BB * CC + g]     = bb;
    out_states[2 * BB * CC + g] = pp;
}

// ---------------------------------------------------------------------------
// S3: replay chunks, emit sigmoid(r)*wkv  (round-1 verbatim)
// ---------------------------------------------------------------------------
__global__ void __launch_bounds__(256) scan_output(
    const float* __restrict__ td, const float* __restrict__ tf)
{
    const int g = blockIdx.x * 256 + threadIdx.x;
    const int c = g & (CC - 1);
    const int chunk = (g >> 10) & (NCHUNK - 1);
    const int b = g >> 16;

    const float w = __expf(td[c]);
    const float u = tf[c];
    const int idx = (b * NCHUNK + chunk) * CC + c;
    const int base = (b * TT + chunk * LCH) * CC + c;

    float aa = g_ia[idx], bb = g_ib[idx], pp = g_ip[idx];
    #pragma unroll 4
    for (int l = 0; l < LCH; l++) {
        float kt = g_k[base + l * CC];
        float vt = g_v[base + l * CC];
        float rt = g_r[base + l * CC];
        float ww = u + kt;
        float p  = fmaxf(pp, ww);
        float e1 = __expf(pp - p);
        float e2 = __expf(ww - p);
        float wkv = (e1 * aa + e2 * vt) / (e1 * bb + e2);
        g_rwkv[base + l * CC] = rt * wkv;
        float ww2 = pp - w;
        float p2  = fmaxf(ww2, kt);
        float e1b = __expf(ww2 - p2);
        float e2b = __expf(kt - p2);
        aa = e1b * aa + e2b * vt;
        bb = e1b * bb + e2b;
        pp = p2;
    }
}

// ---------------------------------------------------------------------------
// Launcher (round-1 verbatim: 4 GEMM launches, no fusion)
// ---------------------------------------------------------------------------
extern "C" void kernel_launch(void* const* d_in, const int* in_sizes, int n_in,
                              void* d_out, int out_size)
{
    const float* x        = (const float*)d_in[0];
    const float* key_w    = (const float*)d_in[1];
    const float* value_w  = (const float*)d_in[2];
    const float* recept_w = (const float*)d_in[3];
    const float* output_w = (const float*)d_in[4];
    const float* td       = (const float*)d_in[5];  // time_decay
    const float* tf       = (const float*)d_in[6];  // time_first
    const float* aa0      = (const float*)d_in[7];
    const float* bb0      = (const float*)d_in[8];
    const float* pp0      = (const float*)d_in[9];
    float* out = (float*)d_out;

    dim3 gg(MTOT / 128, CC / 128);   // 128 x 8

    // projections
    gemm_tf32<<<gg, 256>>>(x, key_w,    nullptr, 0, 0, 0);
    gemm_tf32<<<gg, 256>>>(x, value_w,  nullptr, 0, 1, 0);
    gemm_tf32<<<gg, 256>>>(x, recept_w, nullptr, 0, 2, 1);

    // chunked WKV scan
    scan_chunk_state<<<(BB * NCHUNK * CC) / 256, 256>>>(td);
    scan_combine<<<(BB * CC) / 256, 256>>>(td, aa0, bb0, pp0,
                                           out + (size_t)MTOT * CC);
    scan_output<<<(BB * NCHUNK * CC) / 256, 256>>>(td, tf);

    // output projection
    gemm_tf32<<<gg, 256>>>(nullptr, output_w, out, 1, 3, 0);
}